// round 17
// baseline (speedup 1.0000x reference)
#include <cuda_runtime.h>
#include <cuda_fp16.h>
#include <cstdint>

// Problem constants
#define Bq    16384
#define Dd    128
#define Hh    4
#define Ee    8
#define Nn    65536        // B*H tokens
#define OD    32           // ODIM = D/H
#define NSLOT 131072       // Nn * TOPK
#define NGB   128          // gating blocks = batches of 128 b's
#define NBIN  32           // (expert, head) bins

typedef unsigned long long ull;

// packed f32x2 FMA (projgate; per-lane accumulation order identical to scalar)
#define FMA2(acc, a2, b2) \
    asm("fma.rn.f32x2 %0, %1, %2, %0;" : "+l"(acc) : "l"(a2), "l"(b2))
#define PACKBC(d, s) \
    asm("mov.b64 %0, {%1, %1};" : "=l"(d) : "f"(s))

// warp-level fp16 MMA, fp32 accumulate (sm_80+ base ISA; no arch suffix needed)
#define MMA16816(d, a0, a1, a2, a3, b0, b1) \
    asm volatile("mma.sync.aligned.m16n8k16.row.col.f32.f16.f16.f32 " \
        "{%0,%1,%2,%3}, {%4,%5,%6,%7}, {%8,%9}, {%0,%1,%2,%3};" \
        : "+f"((d)[0]), "+f"((d)[1]), "+f"((d)[2]), "+f"((d)[3]) \
        : "r"(a0), "r"(a1), "r"(a2), "r"(a3), "r"(b0), "r"(b1))

// ---------------- device scratch (no allocs allowed) ----------------
__device__ float g_bM[NBIN * Dd];        // folded bias (bq_h @ W1_e + b1_e)
__device__ float g_v [NBIN * Dd];        // W2_e @ Wout_chunk_h
__device__ float g_c [NBIN];             // b2_e . Wout_chunk_h
__device__ float g_bg[NBIN];             // bk_h @ Wg contribution to logit (e,h)
__device__ __align__(16) __half g_Mhi[NBIN * Dd * Dd];  // 1 MB : M^T hi [bin][hid][d]
__device__ __align__(16) __half g_Mlo[NBIN * Dd * Dd];  // 1 MB : M^T lo
__device__ int   g_topi [NSLOT];
__device__ float g_topw [NSLOT];
__device__ int   g_srank[NSLOT];         // rank within (b-block, bin)
__device__ int   g_blkcnt [NGB * NBIN];
__device__ int   g_blkbase[NGB * NBIN];  // per-bin exclusive prefix over blocks
__device__ int   g_off[NBIN + 1];
__device__ int   g_count[NBIN];
__device__ int   g_tileoff[NBIN + 1];
__device__ float g_sump[Ee];
__device__ int   g_cnt1[Ee];
__device__ float g_aux;
__device__ int   g_perm[NSLOT];          // bin-sorted list of (token*2+slot)
__device__ float g_contrib[NSLOT];       // per-slot weighted scalar contribution

// ---------------- init ----------------
__global__ void k_init() {
    int t = threadIdx.x;
    if (t < Ee) { g_sump[t] = 0.f; g_cnt1[t] = 0; }
}

// ---------------- fold: M = Wq_h @ W1_e, emitted as fp16 hi/lo M^T[hid][d] --------
// 64 blocks: (eh, half). 256 threads, 8x4 micro over a 128x64 slice of hid.
__global__ void k_fold(const float* __restrict__ Wq, const float* __restrict__ W1) {
    extern __shared__ float sm[];
    float* As = sm;               // 128 x 132 : Wq_h  (rows d, cols c)
    float* Bs = sm + 128 * 132;   // 128 x 64  : W1_e  (rows c, cols hid-slice)
    const int tid = threadIdx.x;
    const int bb = blockIdx.x;
    const int eh = bb >> 1;
    const int e  = eh >> 2, h = eh & 3;
    const int n0 = (bb & 1) * 64;

    for (int i = tid; i < 128 * 32; i += 256) {
        int r = i >> 5, c = (i & 31) << 2;
        *(float4*)(As + r * 132 + c) = *(const float4*)(Wq + (size_t)r * 512 + h * 128 + c);
    }
    for (int i = tid; i < 128 * 16; i += 256) {
        int r = i >> 4, c = (i & 15) << 2;
        *(float4*)(Bs + r * 64 + c) =
            *(const float4*)(W1 + (size_t)e * 16384 + (size_t)r * 128 + n0 + c);
    }
    __syncthreads();

    const int tx = tid & 15, ty = tid >> 4;
    float acc[8][4];
#pragma unroll
    for (int i = 0; i < 8; i++)
#pragma unroll
        for (int j = 0; j < 4; j++) acc[i][j] = 0.f;

#pragma unroll 8
    for (int k = 0; k < 128; k++) {
        float4 b = *(const float4*)(Bs + k * 64 + tx * 4);
#pragma unroll
        for (int i = 0; i < 8; i++) {
            float a = As[(ty + 16 * i) * 132 + k];
            acc[i][0] = fmaf(a, b.x, acc[i][0]);
            acc[i][1] = fmaf(a, b.y, acc[i][1]);
            acc[i][2] = fmaf(a, b.z, acc[i][2]);
            acc[i][3] = fmaf(a, b.w, acc[i][3]);
        }
    }

    // scatter hi/lo fp16 of M^T[hid][d]
#pragma unroll
    for (int i = 0; i < 8; i++) {
        int d = ty + 16 * i;
#pragma unroll
        for (int jj = 0; jj < 4; jj++) {
            int hid = n0 + tx * 4 + jj;
            float val = acc[i][jj];
            __half hb = __float2half_rn(val);
            __half lb = __float2half_rn(val - __half2float(hb));
            size_t o = (size_t)eh * 16384 + (size_t)hid * 128 + d;
            g_Mhi[o] = hb;
            g_Mlo[o] = lb;
        }
    }
}

// ---------------- fold small: bM, v, c, bg per (e,h) ----------------
__global__ void k_fold_small(const float* __restrict__ bq, const float* __restrict__ W1,
                             const float* __restrict__ b1, const float* __restrict__ W2,
                             const float* __restrict__ b2, const float* __restrict__ Wout,
                             const float* __restrict__ bk, const float* __restrict__ Wg) {
    const int eh = blockIdx.x;
    const int e = eh >> 2, h = eh & 3;
    const int k = threadIdx.x;   // 0..127
    float s = b1[e * 128 + k];
    for (int j = 0; j < 128; j++)
        s = fmaf(bq[h * 128 + j], W1[(size_t)e * 16384 + (size_t)j * 128 + k], s);
    g_bM[eh * 128 + k] = s;
    float v = 0.f;
    for (int t = 0; t < 32; t++)
        v = fmaf(W2[(size_t)e * 4096 + (size_t)k * 32 + t], Wout[h * 32 + t], v);
    g_v[eh * 128 + k] = v;
    if (k == 0) {
        float c = 0.f;
        for (int t = 0; t < 32; t++)
            c = fmaf(b2[e * 32 + t], Wout[h * 32 + t], c);
        g_c[eh] = c;
    }
    if (k == 1) {
        float s2 = 0.f;
        for (int c = 0; c < 128; c++)
            s2 = fmaf(bk[h * 128 + c], Wg[c * 8 + e], s2);
        g_bg[eh] = s2;
    }
}

// ---------------- fused projection + gating (fp32-exact, unchanged) ---------------
__global__ void __launch_bounds__(256, 2)
k_projgate(const float* __restrict__ X, const float* __restrict__ Wk,
           const float* __restrict__ Wg) {
    extern __shared__ float sm[];
    float* As = sm;               // 128 x 132 : X tile, reused for C (gate feats)
    float* Bs = sm + 128 * 132;   // 64 x 128  : Wk k-chunk
    __shared__ int   srank[Ee];
    __shared__ float ssum [Ee];
    __shared__ int   scnt1[Ee];
    const int tid = threadIdx.x;
    const int h  = blockIdx.x;
    const int by = blockIdx.y;
    const int m0 = by * 128;
    const int n0 = h * 128;
    if (tid < Ee) { srank[tid] = 0; ssum[tid] = 0.f; scnt1[tid] = 0; }

    for (int i = tid; i < 128 * 32; i += 256) {
        int r = i >> 5, c = (i & 31) << 2;
        *(float4*)(As + r * 132 + c) = *(const float4*)(X + (size_t)(m0 + r) * Dd + c);
    }

    const int tx = tid & 15, ty = tid >> 4;
    ull acc2[8][4];
#pragma unroll
    for (int i = 0; i < 8; i++)
#pragma unroll
        for (int j = 0; j < 4; j++) acc2[i][j] = 0ull;

#pragma unroll
    for (int kc = 0; kc < 2; kc++) {
        for (int i = tid; i < 64 * 32; i += 256) {
            int r = i >> 5, c = (i & 31) << 2;
            *(float4*)(Bs + r * 128 + c) =
                *(const float4*)(Wk + (size_t)(kc * 64 + r) * 512 + n0 + c);
        }
        __syncthreads();
#pragma unroll 8
        for (int kk = 0; kk < 64; kk++) {
            ulonglong2 bp0 = *(const ulonglong2*)(Bs + kk * 128 + tx * 8);
            ulonglong2 bp1 = *(const ulonglong2*)(Bs + kk * 128 + tx * 8 + 4);
            int k = kc * 64 + kk;
#pragma unroll
            for (int i = 0; i < 8; i++) {
                float a = As[(ty + 16 * i) * 132 + k];
                ull ap; PACKBC(ap, a);
                FMA2(acc2[i][0], ap, bp0.x);
                FMA2(acc2[i][1], ap, bp0.y);
                FMA2(acc2[i][2], ap, bp1.x);
                FMA2(acc2[i][3], ap, bp1.y);
            }
        }
        __syncthreads();
    }

#pragma unroll
    for (int i = 0; i < 8; i++) {
        int m = ty + 16 * i;
#pragma unroll
        for (int j = 0; j < 4; j++)
            *(ull*)(As + m * 132 + tx * 8 + 2 * j) = acc2[i][j];
    }
    __syncthreads();

    const int lane = tid & 31, warp = tid >> 5;
    float wr[4][8];
#pragma unroll
    for (int i = 0; i < 4; i++)
#pragma unroll
        for (int e = 0; e < 8; e++)
            wr[i][e] = Wg[(lane * 4 + i) * 8 + e];
    float blg[8];
#pragma unroll
    for (int e = 0; e < 8; e++) blg[e] = g_bg[e * 4 + h];

    float lsum[8];
#pragma unroll
    for (int e = 0; e < 8; e++) lsum[e] = 0.f;

    for (int it = 0; it < 16; it++) {
        int m = warp * 16 + it;
        float4 gv = *(const float4*)(As + m * 132 + lane * 4);
        float p[8];
#pragma unroll
        for (int e = 0; e < 8; e++)
            p[e] = gv.x * wr[0][e] + gv.y * wr[1][e] + gv.z * wr[2][e] + gv.w * wr[3][e];
#pragma unroll
        for (int off = 16; off; off >>= 1)
#pragma unroll
            for (int e = 0; e < 8; e++)
                p[e] += __shfl_xor_sync(0xffffffffu, p[e], off);
#pragma unroll
        for (int e = 0; e < 8; e++) p[e] += blg[e];
        float mx = p[0];
#pragma unroll
        for (int e = 1; e < 8; e++) mx = fmaxf(mx, p[e]);
        float s = 0.f;
#pragma unroll
        for (int e = 0; e < 8; e++) { p[e] = __expf(p[e] - mx); s += p[e]; }
        float inv = 1.f / s;
#pragma unroll
        for (int e = 0; e < 8; e++) p[e] *= inv;
        int i1 = 0; float v1 = p[0];
#pragma unroll
        for (int e = 1; e < 8; e++) if (p[e] > v1) { v1 = p[e]; i1 = e; }
        int i2 = -1; float v2 = -1e30f;
#pragma unroll
        for (int e = 0; e < 8; e++) if (e != i1 && p[e] > v2) { v2 = p[e]; i2 = e; }
#pragma unroll
        for (int e = 0; e < 8; e++) lsum[e] += p[e];

        if (lane == 0) {
            int n = (m0 + m) * 4 + h;
            atomicAdd(&scnt1[i1], 1);
            int r1 = atomicAdd(&srank[i1], 1);
            int r2 = atomicAdd(&srank[i2], 1);
            float wsum = v1 + v2;
            g_topi[2 * n]     = i1;  g_topi[2 * n + 1] = i2;
            g_topw[2 * n]     = v1 / wsum;
            g_topw[2 * n + 1] = v2 / wsum;
            g_srank[2 * n]     = r1;
            g_srank[2 * n + 1] = r2;
        }
    }
    if (lane == 0)
#pragma unroll
        for (int e = 0; e < 8; e++) atomicAdd(&ssum[e], lsum[e]);
    __syncthreads();
    if (tid < Ee) {
        g_blkcnt[by * NBIN + tid * 4 + h] = srank[tid];
        atomicAdd(&g_sump[tid], ssum[tid]);
        atomicAdd(&g_cnt1[tid], scnt1[tid]);
    }
}

// ---------------- phase2: prefix sums, offsets, tile map, aux loss ----------------
__global__ void k_phase2() {
    const int tid = threadIdx.x;
    if (tid < NBIN) {
        int base = 0;
        for (int b = 0; b < NGB; b++) {
            int c = g_blkcnt[b * NBIN + tid];
            g_blkbase[b * NBIN + tid] = base;
            base += c;
        }
        g_count[tid] = base;
    }
    __syncthreads();
    if (tid == 0) {
        int off = 0, toff = 0;
        for (int bin = 0; bin < NBIN; bin++) {
            g_off[bin] = off; g_tileoff[bin] = toff;
            off  += g_count[bin];
            toff += (g_count[bin] + 63) >> 6;     // 64-slot tiles
        }
        g_off[NBIN] = off; g_tileoff[NBIN] = toff;
        float aux = 0.f;
        for (int e = 0; e < Ee; e++)
            aux += (float)g_cnt1[e] * g_sump[e];
        g_aux = (float)Ee * aux / ((float)Nn * (float)Nn);
    }
}

// ---------------- scatter slots into bin-sorted list ----------------
__global__ void k_scatter() {
    int idx = blockIdx.x * blockDim.x + threadIdx.x;
    if (idx >= NSLOT) return;
    int n = idx >> 1;
    int bin = g_topi[idx] * 4 + (n & 3);
    int gb  = idx >> 10;
    int pos = g_off[bin] + g_blkbase[gb * NBIN + bin] + g_srank[idx];
    g_perm[pos] = idx;
}

// ---------------- HMMA expert: 64-slot tiles, 128 threads, occ 2 ------------------
// warp = one 16-row M-tile; 16 N-tiles x 8 K-steps x 3 passes = 384 MMA/warp.
#define PADW   136              // fp16 per padded row (stride 68 words: conflict-free)
#define SM_AHI 0                // 64 x 136 fp16 = 17408 B
#define SM_ALO 17408
#define SM_BHI 34816            // 128 x 136 fp16 = 34816 B
#define SM_BLO 69632
#define SM_V   104448
#define SM_BM  104960
#define SM_W   105472
#define SM_ENC 105728
#define SM_TOT 105984

__global__ void __launch_bounds__(128, 2)
k_expert(const float* __restrict__ x) {
    extern __shared__ unsigned char smc[];
    const int tid = threadIdx.x;
    const int wid = tid >> 5, lane = tid & 31;

    const int t = blockIdx.x;
    if (t >= g_tileoff[NBIN]) return;
    int bin = 0;
#pragma unroll
    for (int i = 0; i < NBIN - 1; i++)
        if (t >= g_tileoff[i + 1]) bin++;
    const int tile = t - g_tileoff[bin];
    const int i0 = tile << 6;
    const int nvalid = min(64, g_count[bin] - i0);

    float* vSp = (float*)(smc + SM_V);
    float* bSp = (float*)(smc + SM_BM);
    float* sWp = (float*)(smc + SM_W);
    int*  sEnc = (int*)  (smc + SM_ENC);

    if (tid < 64) {
        int j = g_off[bin] + i0 + tid;
        if (j > NSLOT - 1) j = NSLOT - 1;   // tail rows: safe garbage, never stored
        int enc = g_perm[j];
        sEnc[tid] = enc;
        sWp[tid]  = g_topw[enc];
    }
    vSp[tid] = g_v [bin * 128 + tid];
    bSp[tid] = g_bM[bin * 128 + tid];
    __syncthreads();

    // B images: copy M^T hi/lo into padded rows (17 uint4 per 16-uint4 row)
    {
        const uint4* sh = (const uint4*)(g_Mhi + (size_t)bin * 16384);
        const uint4* sl = (const uint4*)(g_Mlo + (size_t)bin * 16384);
        uint4* dh = (uint4*)(smc + SM_BHI);
        uint4* dl = (uint4*)(smc + SM_BLO);
        for (int i = tid; i < 2048; i += 128) {
            int r = i >> 4, c = i & 15;
            dh[r * 17 + c] = sh[i];
            dl[r * 17 + c] = sl[i];
        }
    }
    // A images: gather token rows, split to fp16 hi/lo (2 threads per row)
    {
        int r = tid >> 1, half = tid & 1;
        const float* xr = x + (size_t)(sEnc[r] >> 3) * 128 + half * 64;
        __half* ah = (__half*)(smc + SM_AHI) + r * PADW + half * 64;
        __half* al = (__half*)(smc + SM_ALO) + r * PADW + half * 64;
#pragma unroll
        for (int i = 0; i < 16; i++) {
            float4 v4 = *(const float4*)(xr + i * 4);
            __half2 h0 = __floats2half2_rn(v4.x, v4.y);
            __half2 h1 = __floats2half2_rn(v4.z, v4.w);
            __half2 l0 = __floats2half2_rn(v4.x - __half2float(h0.x),
                                           v4.y - __half2float(h0.y));
            __half2 l1 = __floats2half2_rn(v4.z - __half2float(h1.x),
                                           v4.w - __half2float(h1.y));
            *(__half2*)(ah + i * 4)     = h0;
            *(__half2*)(ah + i * 4 + 2) = h1;
            *(__half2*)(al + i * 4)     = l0;
            *(__half2*)(al + i * 4 + 2) = l1;
        }
    }
    __syncthreads();

    const __half* Ah = (const __half*)(smc + SM_AHI);
    const __half* Al = (const __half*)(smc + SM_ALO);
    const __half* Bh = (const __half*)(smc + SM_BHI);
    const __half* Bl = (const __half*)(smc + SM_BLO);
    const int g   = lane >> 2;
    const int tig = lane & 3;
    const int ar0 = (wid * 16 + g) * PADW;
    const int ar1 = ar0 + 8 * PADW;

    float acc[16][4];
#pragma unroll
    for (int tt = 0; tt < 16; tt++)
#pragma unroll
        for (int j = 0; j < 4; j++) acc[tt][j] = 0.f;

#pragma unroll 1
    for (int ks = 0; ks < 8; ks++) {
        const int kc = ks * 16 + 2 * tig;
        uint32_t ah0 = *(const uint32_t*)(Ah + ar0 + kc);
        uint32_t ah1 = *(const uint32_t*)(Ah + ar1 + kc);
        uint32_t ah2 = *(const uint32_t*)(Ah + ar0 + kc + 8);
        uint32_t ah3 = *(const uint32_t*)(Ah + ar1 + kc + 8);
        uint32_t al0 = *(const uint32_t*)(Al + ar0 + kc);
        uint32_t al1 = *(const uint32_t*)(Al + ar1 + kc);
        uint32_t al2 = *(const uint32_t*)(Al + ar0 + kc + 8);
        uint32_t al3 = *(const uint32_t*)(Al + ar1 + kc + 8);
#pragma unroll
        for (int tt = 0; tt < 16; tt++) {
            int br = (tt * 8 + g) * PADW + kc;
            uint32_t bh0 = *(const uint32_t*)(Bh + br);
            uint32_t bh1 = *(const uint32_t*)(Bh + br + 8);
            uint32_t bl0 = *(const uint32_t*)(Bl + br);
            uint32_t bl1 = *(const uint32_t*)(Bl + br + 8);
            MMA16816(acc[tt], ah0, ah1, ah2, ah3, bh0, bh1);
            MMA16816(acc[tt], ah0, ah1, ah2, ah3, bl0, bl1);
            MMA16816(acc[tt], al0, al1, al2, al3, bh0, bh1);
        }
    }

    // epilogue: lane owns rows (wid*16+g, +8), cols {8tt+2tig, +1}
    float d0 = 0.f, d1 = 0.f;
#pragma unroll
    for (int tt = 0; tt < 16; tt++) {
        int c = tt * 8 + 2 * tig;
        float b0 = bSp[c], b1 = bSp[c + 1];
        float v0 = vSp[c], v1 = vSp[c + 1];
        d0 = fmaf(fmaxf(acc[tt][0] + b0, 0.f), v0, d0);
        d0 = fmaf(fmaxf(acc[tt][1] + b1, 0.f), v1, d0);
        d1 = fmaf(fmaxf(acc[tt][2] + b0, 0.f), v0, d1);
        d1 = fmaf(fmaxf(acc[tt][3] + b1, 0.f), v1, d1);
    }
    d0 += __shfl_xor_sync(0xffffffffu, d0, 1);
    d0 += __shfl_xor_sync(0xffffffffu, d0, 2);
    d1 += __shfl_xor_sync(0xffffffffu, d1, 1);
    d1 += __shfl_xor_sync(0xffffffffu, d1, 2);
    if (tig == 0) {
        float ceh = g_c[bin];
        int r0 = wid * 16 + g, r1 = r0 + 8;
        if (r0 < nvalid) g_contrib[sEnc[r0]] = sWp[r0] * (d0 + ceh);
        if (r1 < nvalid) g_contrib[sEnc[r1]] = sWp[r1] * (d1 + ceh);
    }
}

// ---------------- final: out[b] = bout + sum of 8 slot contributions ----------------
__global__ void k_final(const float* __restrict__ bout, float* __restrict__ out,
                        int out_size) {
    int b = blockIdx.x * blockDim.x + threadIdx.x;
    float4 c0 = *(const float4*)(g_contrib + (size_t)b * 8);
    float4 c1 = *(const float4*)(g_contrib + (size_t)b * 8 + 4);
    out[b] = bout[0] + ((c0.x + c0.y) + (c0.z + c0.w)) +
                       ((c1.x + c1.y) + (c1.z + c1.w));
    if (b == 0)
        for (int i = Bq; i < out_size; i++) out[i] = g_aux;   // aux loss scalar
}

// ---------------- launch ----------------
extern "C" void kernel_launch(void* const* d_in, const int* in_sizes, int n_in,
                              void* d_out, int out_size) {
    const float* x    = (const float*)d_in[0];
    const float* Wq   = (const float*)d_in[1];
    const float* bq   = (const float*)d_in[2];
    const float* Wk   = (const float*)d_in[3];
    const float* bk   = (const float*)d_in[4];
    const float* Wg   = (const float*)d_in[5];
    const float* W1   = (const float*)d_in[6];
    const float* b1   = (const float*)d_in[7];
    const float* W2   = (const float*)d_in[8];
    const float* b2   = (const float*)d_in[9];
    const float* Wout = (const float*)d_in[10];
    const float* bout = (const float*)d_in[11];
    float* out = (float*)d_out;

    const int smFold = (128 * 132 + 128 * 64) * 4;  // 100,352 B
    const int smProj = (128 * 132 + 64 * 128) * 4;  // 100,352 B
    cudaFuncSetAttribute(k_fold,     cudaFuncAttributeMaxDynamicSharedMemorySize, smFold);
    cudaFuncSetAttribute(k_projgate, cudaFuncAttributeMaxDynamicSharedMemorySize, smProj);
    cudaFuncSetAttribute(k_expert,   cudaFuncAttributeMaxDynamicSharedMemorySize, SM_TOT);

    k_init<<<1, 32>>>();
    k_fold<<<64, 256, smFold>>>(Wq, W1);
    k_fold_small<<<NBIN, 128>>>(bq, W1, b1, W2, b2, Wout, bk, Wg);
    dim3 gp(4, 128);
    k_projgate<<<gp, 256, smProj>>>(x, Wk, Wg);
    k_phase2<<<1, 64>>>();
    k_scatter<<<NSLOT / 256, 256>>>();
    k_expert<<<2080, 128, SM_TOT>>>(x);   // sum of per-bin ceil(count/64) <= 2080
    k_final<<<Bq / 256, 256>>>(bout, out, out_size);
}